// round 1
// baseline (speedup 1.0000x reference)
#include <cuda_runtime.h>
#include <math.h>

// Problem constants (from reference): N=50000, E=800000, IN=128, HID=256, HEADS=4
#define NMAX 50000
#define EMAX 800000

// ---------------- device scratch (no allocations allowed) ----------------
__device__ float g_h  [NMAX * 256];   // transformed features (layer1 h1, reused as h2)
__device__ float g_x2 [NMAX * 256];   // layer1 aggregate -> elu -> layer2 input
__device__ float g_as [NMAX * 4];
__device__ float g_ad [NMAX * 4];
__device__ float g_m  [NMAX * 4];
__device__ float g_den[NMAX * 4];

// ---------------- helpers ----------------
__device__ __forceinline__ void atomicMaxF(float* addr, float v) {
    // monotone bit trick: positive floats ordered as ints, negative floats
    // reverse-ordered as unsigned. Init must be -INF (0xFF800000).
    if (v >= 0.0f) atomicMax((int*)addr, __float_as_int(v));
    else           atomicMin((unsigned int*)addr, __float_as_uint(v));
}

__global__ void fill_kernel(float* __restrict__ p, float v, int n) {
    int i = blockIdx.x * blockDim.x + threadIdx.x;
    if (i < n) p[i] = v;
}

// ---------------- fp32 tiled GEMM: C[M,N] = A[M,K] @ B[K,N] ----------------
// BM=BN=64, BK=16, 256 threads, 4x4 micro-tile per thread.
// Requires: K % 16 == 0, N % 64 == 0 (true here: K in {128,256}, N=256).
__global__ __launch_bounds__(256) void sgemm(
    const float* __restrict__ A, const float* __restrict__ B,
    float* __restrict__ C, int M, int N, int K)
{
    __shared__ float As[16][64];   // As[k][m]
    __shared__ float Bs[16][64];   // Bs[k][n]
    const int bm = blockIdx.y * 64;
    const int bn = blockIdx.x * 64;
    const int tx = threadIdx.x & 15;
    const int ty = threadIdx.x >> 4;

    float acc[4][4];
#pragma unroll
    for (int i = 0; i < 4; i++)
#pragma unroll
        for (int j = 0; j < 4; j++) acc[i][j] = 0.0f;

    for (int k0 = 0; k0 < K; k0 += 16) {
#pragma unroll
        for (int i = 0; i < 4; i++) {
            int idx = threadIdx.x + i * 256;     // 0..1023
            int r = idx >> 4, c = idx & 15;      // A tile is 64 rows x 16 cols
            As[c][r] = (bm + r < M) ? A[(size_t)(bm + r) * K + k0 + c] : 0.0f;
        }
#pragma unroll
        for (int i = 0; i < 4; i++) {
            int idx = threadIdx.x + i * 256;
            int r = idx >> 6, c = idx & 63;      // B tile is 16 rows x 64 cols
            Bs[r][c] = B[(size_t)(k0 + r) * N + bn + c];
        }
        __syncthreads();
#pragma unroll
        for (int k = 0; k < 16; k++) {
            float4 a4 = *(const float4*)&As[k][ty * 4];
            float4 b4 = *(const float4*)&Bs[k][tx * 4];
            float a[4] = {a4.x, a4.y, a4.z, a4.w};
            float b[4] = {b4.x, b4.y, b4.z, b4.w};
#pragma unroll
            for (int i = 0; i < 4; i++)
#pragma unroll
                for (int j = 0; j < 4; j++) acc[i][j] += a[i] * b[j];
        }
        __syncthreads();
    }
#pragma unroll
    for (int i = 0; i < 4; i++) {
        int r = bm + ty * 4 + i;
        if (r < M) {
            float4 v = make_float4(acc[i][0], acc[i][1], acc[i][2], acc[i][3]);
            *(float4*)&C[(size_t)r * N + bn + tx * 4] = v;
        }
    }
}

// ---------------- per-node attention scalars: alpha_src/dst = <h, a> ----------------
// One warp per (node, head).
template <int H, int C>
__global__ __launch_bounds__(256) void alpha_kernel(
    const float* __restrict__ h, const float* __restrict__ a_src,
    const float* __restrict__ a_dst, float* __restrict__ as_out,
    float* __restrict__ ad_out, int n)
{
    int warp = (blockIdx.x * blockDim.x + threadIdx.x) >> 5;
    int lane = threadIdx.x & 31;
    if (warp >= n * H) return;
    int node = warp / H, head = warp % H;
    const float* hp  = h + (size_t)node * (H * C) + head * C;
    const float* asp = a_src + head * C;
    const float* adp = a_dst + head * C;
    float s1 = 0.0f, s2 = 0.0f;
#pragma unroll
    for (int c = lane; c < C; c += 32) {
        float v = hp[c];
        s1 += v * asp[c];
        s2 += v * adp[c];
    }
#pragma unroll
    for (int o = 16; o > 0; o >>= 1) {
        s1 += __shfl_xor_sync(0xFFFFFFFFu, s1, o);
        s2 += __shfl_xor_sync(0xFFFFFFFFu, s2, o);
    }
    if (lane == 0) { as_out[warp] = s1; ad_out[warp] = s2; }
}

// ---------------- edge pass A: segment max of leaky_relu(as[src]+ad[dst]) ----------------
template <int H>
__global__ __launch_bounds__(256) void edge_max(
    const int* __restrict__ src, const int* __restrict__ dst,
    const float* __restrict__ as, const float* __restrict__ ad,
    float* __restrict__ m, int E, int n)
{
    int e = blockIdx.x * blockDim.x + threadIdx.x;
    int ET = E + n;
    if (e >= ET) return;
    int s, d;
    if (e < E) { s = src[e]; d = dst[e]; } else { s = d = e - E; }
#pragma unroll
    for (int h = 0; h < H; h++) {
        float v = as[s * H + h] + ad[d * H + h];
        v = v > 0.0f ? v : 0.2f * v;
        atomicMaxF(&m[d * H + h], v);
    }
}

// ---------------- edge pass B: denom = segment sum of exp(e - m[dst]) ----------------
template <int H>
__global__ __launch_bounds__(256) void edge_sum(
    const int* __restrict__ src, const int* __restrict__ dst,
    const float* __restrict__ as, const float* __restrict__ ad,
    const float* __restrict__ m, float* __restrict__ den, int E, int n)
{
    int e = blockIdx.x * blockDim.x + threadIdx.x;
    int ET = E + n;
    if (e >= ET) return;
    int s, d;
    if (e < E) { s = src[e]; d = dst[e]; } else { s = d = e - E; }
#pragma unroll
    for (int h = 0; h < H; h++) {
        float v = as[s * H + h] + ad[d * H + h];
        v = v > 0.0f ? v : 0.2f * v;
        float w = __expf(v - m[d * H + h]);
        atomicAdd(&den[d * H + h], w);
    }
}

// ---------------- edge pass C: out[dst] += h[src] * alpha ----------------
// 64 threads per edge; each thread handles 4 consecutive channels (float4).
// H*C must be 256 (true for both layers).
template <int H, int C>
__global__ __launch_bounds__(256) void edge_msg(
    const int* __restrict__ src, const int* __restrict__ dst,
    const float* __restrict__ as, const float* __restrict__ ad,
    const float* __restrict__ m, const float* __restrict__ den,
    const float* __restrict__ hfeat, float* __restrict__ out, int E, int n)
{
    int gid = blockIdx.x * blockDim.x + threadIdx.x;
    int e = gid >> 6;
    int t = gid & 63;
    int ET = E + n;
    if (e >= ET) return;
    int s, d;
    if (e < E) { s = src[e]; d = dst[e]; } else { s = d = e - E; }

    const int head = (t * 4) / C;   // compile-time-simplified
    float v = as[s * H + head] + ad[d * H + head];
    v = v > 0.0f ? v : 0.2f * v;
    float alpha = __expf(v - m[d * H + head]) / (den[d * H + head] + 1e-16f);

    float4 hv = __ldg((const float4*)hfeat + (size_t)s * 64 + t);
    float* op = out + ((size_t)d * 64 + t) * 4;
    atomicAdd(op + 0, hv.x * alpha);
    atomicAdd(op + 1, hv.y * alpha);
    atomicAdd(op + 2, hv.z * alpha);
    atomicAdd(op + 3, hv.w * alpha);
}

// ---------------- epilogues ----------------
__global__ void bias_elu_kernel(float* __restrict__ x, const float* __restrict__ b, int total) {
    int i = blockIdx.x * blockDim.x + threadIdx.x;
    if (i < total) {
        float v = x[i] + b[i & 255];
        x[i] = v > 0.0f ? v : expm1f(v);
    }
}

__global__ void add_bias_kernel(float* __restrict__ out, const float* __restrict__ b, int total) {
    int i = blockIdx.x * blockDim.x + threadIdx.x;
    if (i < total) out[i] += b[i & 255];
}

// ---------------- launch ----------------
extern "C" void kernel_launch(void* const* d_in, const int* in_sizes, int n_in,
                              void* d_out, int out_size)
{
    const float* x   = (const float*)d_in[0];
    const int*   ei  = (const int*)  d_in[1];
    const float* W1  = (const float*)d_in[2];
    const float* as1 = (const float*)d_in[3];
    const float* ad1 = (const float*)d_in[4];
    const float* b1  = (const float*)d_in[5];
    const float* W2  = (const float*)d_in[6];
    const float* as2 = (const float*)d_in[7];
    const float* ad2 = (const float*)d_in[8];
    const float* b2  = (const float*)d_in[9];
    float* out = (float*)d_out;

    const int N = in_sizes[0] / 128;
    const int E = in_sizes[1] / 2;
    const int* src = ei;
    const int* dst = ei + E;
    const int ET = E + N;
    const int F = N * 256;

    float *h, *x2, *as, *ad, *m, *den;
    cudaGetSymbolAddress((void**)&h,   g_h);
    cudaGetSymbolAddress((void**)&x2,  g_x2);
    cudaGetSymbolAddress((void**)&as,  g_as);
    cudaGetSymbolAddress((void**)&ad,  g_ad);
    cudaGetSymbolAddress((void**)&m,   g_m);
    cudaGetSymbolAddress((void**)&den, g_den);

    const dim3 gemm_grid(256 / 64, (N + 63) / 64);
    const float NEG_INF = -INFINITY;

    // ================= layer 1: GATConv(128 -> 64, heads=4) =================
    sgemm<<<gemm_grid, 256>>>(x, W1, h, N, 256, 128);
    alpha_kernel<4, 64><<<(N * 4 * 32 + 255) / 256, 256>>>(h, as1, ad1, as, ad, N);
    fill_kernel<<<(N * 4 + 255) / 256, 256>>>(m, NEG_INF, N * 4);
    fill_kernel<<<(N * 4 + 255) / 256, 256>>>(den, 0.0f, N * 4);
    fill_kernel<<<(F + 255) / 256, 256>>>(x2, 0.0f, F);
    edge_max<4><<<(ET + 255) / 256, 256>>>(src, dst, as, ad, m, E, N);
    edge_sum<4><<<(ET + 255) / 256, 256>>>(src, dst, as, ad, m, den, E, N);
    edge_msg<4, 64><<<(ET * 64 + 255) / 256, 256>>>(src, dst, as, ad, m, den, h, x2, E, N);
    bias_elu_kernel<<<(F + 255) / 256, 256>>>(x2, b1, F);

    // ================= layer 2: GATConv(256 -> 256, heads=1) =================
    sgemm<<<gemm_grid, 256>>>(x2, W2, h, N, 256, 256);
    alpha_kernel<1, 256><<<(N * 32 + 255) / 256, 256>>>(h, as2, ad2, as, ad, N);
    fill_kernel<<<(N + 255) / 256, 256>>>(m, NEG_INF, N);
    fill_kernel<<<(N + 255) / 256, 256>>>(den, 0.0f, N);
    fill_kernel<<<(F + 255) / 256, 256>>>(out, 0.0f, F);
    edge_max<1><<<(ET + 255) / 256, 256>>>(src, dst, as, ad, m, E, N);
    edge_sum<1><<<(ET + 255) / 256, 256>>>(src, dst, as, ad, m, den, E, N);
    edge_msg<1, 256><<<(ET * 64 + 255) / 256, 256>>>(src, dst, as, ad, m, den, h, out, E, N);
    add_bias_kernel<<<(F + 255) / 256, 256>>>(out, b2, F);
}

// round 4
// speedup vs baseline: 2.4978x; 2.4978x over previous
#include <cuda_runtime.h>
#include <math.h>

// Problem constants: N=50000, E=800000, IN=128, HID=256, HEADS=4
#define NMAX 50000
#define EMAX 800000

// ---------------- device scratch (no allocations allowed) ----------------
__device__ float g_h   [NMAX * 256];     // transformed features (per-layer)
__device__ float g_x2  [NMAX * 256];     // layer1 output -> layer2 input
__device__ float g_as  [NMAX * 4];
__device__ float g_ad  [NMAX * 4];
__device__ int   g_cnt   [NMAX];
__device__ int   g_rowptr[NMAX + 1];
__device__ int   g_cursor[NMAX];
__device__ int   g_col   [EMAX + NMAX];  // src node per CSR slot (sorted by dst)

// ======================= CSR build =======================
__global__ void fill_int_kernel(int* __restrict__ p, int v, int n) {
    int i = blockIdx.x * blockDim.x + threadIdx.x;
    if (i < n) p[i] = v;
}

__global__ void count_kernel(const int* __restrict__ dst, int* __restrict__ cnt, int E) {
    int i = blockIdx.x * blockDim.x + threadIdx.x;
    if (i < E) atomicAdd(&cnt[dst[i]], 1);
}

// Single-block exclusive scan of cnt[0..n) -> rowptr[0..n], copy into cursor.
__global__ __launch_bounds__(1024) void scan_kernel(
    const int* __restrict__ cnt, int* __restrict__ rowptr,
    int* __restrict__ cursor, int n)
{
    __shared__ int part[1024];
    const int tid = threadIdx.x;
    const int chunk = (n + 1023) >> 10;
    const int begin = tid * chunk;
    const int finish = min(begin + chunk, n);
    int s = 0;
    for (int i = begin; i < finish; i++) s += cnt[i];
    part[tid] = s;
    __syncthreads();
    for (int off = 1; off < 1024; off <<= 1) {
        int v = (tid >= off) ? part[tid - off] : 0;
        __syncthreads();
        part[tid] += v;
        __syncthreads();
    }
    int run = (tid == 0) ? 0 : part[tid - 1];
    for (int i = begin; i < finish; i++) {
        rowptr[i] = run;
        cursor[i] = run;
        run += cnt[i];
    }
    if (tid == 1023) rowptr[n] = part[1023];
}

__global__ void scatter_kernel(
    const int* __restrict__ src, const int* __restrict__ dst,
    int* __restrict__ cursor, int* __restrict__ col, int E, int n)
{
    int i = blockIdx.x * blockDim.x + threadIdx.x;
    int ET = E + n;
    if (i >= ET) return;
    int s, d;
    if (i < E) { s = src[i]; d = dst[i]; } else { s = d = i - E; }
    int p = atomicAdd(&cursor[d], 1);
    col[p] = s;
}

// ======================= fp32 GEMM: C[M,N] = A[M,K] @ B[K,N] =======================
// BM=128, BN=128, BK=16, 256 threads, 8x8 micro-tile. N%128==0, K%16==0 required.
#define BM 128
#define BN 128
#define BK 16
__global__ __launch_bounds__(256) void sgemm(
    const float* __restrict__ A, const float* __restrict__ B,
    float* __restrict__ C, int M, int N, int K)
{
    __shared__ float As[BK][BM + 4];   // transposed, padded vs bank conflicts
    __shared__ float Bs[BK][BN];
    const int bm = blockIdx.y * BM;
    const int bn = blockIdx.x * BN;
    const int tid = threadIdx.x;
    const int tx = tid & 15;           // N dir
    const int ty = tid >> 4;           // M dir

    float acc[8][8];
#pragma unroll
    for (int i = 0; i < 8; i++)
#pragma unroll
        for (int j = 0; j < 8; j++) acc[i][j] = 0.0f;

    for (int k0 = 0; k0 < K; k0 += BK) {
        // load A tile (BM x BK), store transposed: 512 float4s, 2 per thread
#pragma unroll
        for (int i = 0; i < 2; i++) {
            int lin = tid + i * 256;           // 0..511
            int row = lin >> 2;                // 0..127
            int c4  = lin & 3;                 // float4 index in K
            float4 v = make_float4(0.f, 0.f, 0.f, 0.f);
            if (bm + row < M)
                v = *(const float4*)&A[(size_t)(bm + row) * K + k0 + c4 * 4];
            As[c4 * 4 + 0][row] = v.x;
            As[c4 * 4 + 1][row] = v.y;
            As[c4 * 4 + 2][row] = v.z;
            As[c4 * 4 + 3][row] = v.w;
        }
        // load B tile (BK x BN): 512 float4s
#pragma unroll
        for (int i = 0; i < 2; i++) {
            int lin = tid + i * 256;
            int row = lin >> 5;                // 0..15
            int c4  = lin & 31;
            *(float4*)&Bs[row][c4 * 4] =
                *(const float4*)&B[(size_t)(k0 + row) * N + bn + c4 * 4];
        }
        __syncthreads();
#pragma unroll
        for (int k = 0; k < BK; k++) {
            float a[8], b[8];
            *(float4*)&a[0] = *(const float4*)&As[k][ty * 8];
            *(float4*)&a[4] = *(const float4*)&As[k][ty * 8 + 4];
            *(float4*)&b[0] = *(const float4*)&Bs[k][tx * 8];
            *(float4*)&b[4] = *(const float4*)&Bs[k][tx * 8 + 4];
#pragma unroll
            for (int i = 0; i < 8; i++)
#pragma unroll
                for (int j = 0; j < 8; j++) acc[i][j] += a[i] * b[j];
        }
        __syncthreads();
    }
#pragma unroll
    for (int i = 0; i < 8; i++) {
        int r = bm + ty * 8 + i;
        if (r < M) {
            *(float4*)&C[(size_t)r * N + bn + tx * 8]     =
                make_float4(acc[i][0], acc[i][1], acc[i][2], acc[i][3]);
            *(float4*)&C[(size_t)r * N + bn + tx * 8 + 4] =
                make_float4(acc[i][4], acc[i][5], acc[i][6], acc[i][7]);
        }
    }
}

// ============== per-node attention scalars: <h, a_src>, <h, a_dst> ==============
template <int H, int C>
__global__ __launch_bounds__(256) void alpha_kernel(
    const float* __restrict__ hfeat, const float* __restrict__ a_src,
    const float* __restrict__ a_dst, float* __restrict__ as_out,
    float* __restrict__ ad_out, int n)
{
    int warp = (blockIdx.x * blockDim.x + threadIdx.x) >> 5;
    int lane = threadIdx.x & 31;
    if (warp >= n * H) return;
    int node = warp / H, head = warp % H;
    const float* hp  = hfeat + (size_t)node * (H * C) + head * C;
    const float* asp = a_src + head * C;
    const float* adp = a_dst + head * C;
    float s1 = 0.0f, s2 = 0.0f;
#pragma unroll
    for (int c = lane; c < C; c += 32) {
        float v = hp[c];
        s1 += v * asp[c];
        s2 += v * adp[c];
    }
#pragma unroll
    for (int o = 16; o > 0; o >>= 1) {
        s1 += __shfl_xor_sync(0xFFFFFFFFu, s1, o);
        s2 += __shfl_xor_sync(0xFFFFFFFFu, s2, o);
    }
    if (lane == 0) { as_out[warp] = s1; ad_out[warp] = s2; }
}

// ============== gather aggregation: out[d] = sum_e w_e * h[src_e] / sum_e w_e ==============
// One block (256 threads) per dst node; each thread owns one of 256 channels.
// w_e = exp(leaky_relu(as[src] + ad[dst])) — no max-shift needed (|e| bounded).
template <int H, bool ELU>
__global__ __launch_bounds__(256) void aggregate_kernel(
    const int* __restrict__ rowptr, const int* __restrict__ col,
    const float* __restrict__ as, const float* __restrict__ ad,
    const float* __restrict__ hfeat, const float* __restrict__ bias,
    float* __restrict__ out)
{
    const int node = blockIdx.x;
    const int t = threadIdx.x;
    const int C = 256 / H;
    const int head = t / C;

    __shared__ float w_s[32 * H];
    __shared__ int   col_s[32];
    __shared__ float den_s[H];

    const int start = rowptr[node];
    const int end   = rowptr[node + 1];

    float adv[H];
    float den_local[H];
    if (t < 32) {
#pragma unroll
        for (int hh = 0; hh < H; hh++) {
            adv[hh] = ad[node * H + hh];
            den_local[hh] = 0.0f;
        }
    }

    float acc = 0.0f;
    for (int base = start; base < end; base += 32) {
        int cnt = min(32, end - base);
        if (t < 32 && t < cnt) {
            int s = col[base + t];
            col_s[t] = s;
#pragma unroll
            for (int hh = 0; hh < H; hh++) {
                float e = as[s * H + hh] + adv[hh];
                e = e > 0.0f ? e : 0.2f * e;
                float wv = __expf(e);
                w_s[t * H + hh] = wv;
                den_local[hh] += wv;
            }
        }
        __syncthreads();
        int j = 0;
        for (; j + 4 <= cnt; j += 4) {
            int s0 = col_s[j], s1 = col_s[j + 1], s2 = col_s[j + 2], s3 = col_s[j + 3];
            float w0 = w_s[(j    ) * H + head];
            float w1 = w_s[(j + 1) * H + head];
            float w2 = w_s[(j + 2) * H + head];
            float w3 = w_s[(j + 3) * H + head];
            float v0 = hfeat[(size_t)s0 * 256 + t];
            float v1 = hfeat[(size_t)s1 * 256 + t];
            float v2 = hfeat[(size_t)s2 * 256 + t];
            float v3 = hfeat[(size_t)s3 * 256 + t];
            acc += w0 * v0;
            acc += w1 * v1;
            acc += w2 * v2;
            acc += w3 * v3;
        }
        for (; j < cnt; j++)
            acc += w_s[j * H + head] * hfeat[(size_t)col_s[j] * 256 + t];
        __syncthreads();
    }

    if (t < 32) {
#pragma unroll
        for (int hh = 0; hh < H; hh++) {
            float v = den_local[hh];
#pragma unroll
            for (int o = 16; o > 0; o >>= 1) v += __shfl_xor_sync(0xFFFFFFFFu, v, o);
            if (t == 0) den_s[hh] = v;
        }
    }
    __syncthreads();

    float o = acc / (den_s[head] + 1e-16f) + bias[t];
    if (ELU) o = o > 0.0f ? o : expm1f(o);
    out[(size_t)node * 256 + t] = o;
}

// ======================= launch =======================
extern "C" void kernel_launch(void* const* d_in, const int* in_sizes, int n_in,
                              void* d_out, int out_size)
{
    const float* x   = (const float*)d_in[0];
    const int*   ei  = (const int*)  d_in[1];
    const float* W1  = (const float*)d_in[2];
    const float* as1 = (const float*)d_in[3];
    const float* ad1 = (const float*)d_in[4];
    const float* b1  = (const float*)d_in[5];
    const float* W2  = (const float*)d_in[6];
    const float* as2 = (const float*)d_in[7];
    const float* ad2 = (const float*)d_in[8];
    const float* b2  = (const float*)d_in[9];
    float* out = (float*)d_out;

    const int N = in_sizes[0] / 128;
    const int E = in_sizes[1] / 2;
    const int* src = ei;
    const int* dst = ei + E;
    const int ET = E + N;

    float *h, *x2, *as, *ad;
    int *cnt, *rowptr, *cursor, *col;
    cudaGetSymbolAddress((void**)&h,      g_h);
    cudaGetSymbolAddress((void**)&x2,     g_x2);
    cudaGetSymbolAddress((void**)&as,     g_as);
    cudaGetSymbolAddress((void**)&ad,     g_ad);
    cudaGetSymbolAddress((void**)&cnt,    g_cnt);
    cudaGetSymbolAddress((void**)&rowptr, g_rowptr);
    cudaGetSymbolAddress((void**)&cursor, g_cursor);
    cudaGetSymbolAddress((void**)&col,    g_col);

    // ---- CSR build (counts init to 1 = self-loop) ----
    fill_int_kernel<<<(N + 255) / 256, 256>>>(cnt, 1, N);
    count_kernel<<<(E + 255) / 256, 256>>>(dst, cnt, E);
    scan_kernel<<<1, 1024>>>(cnt, rowptr, cursor, N);
    scatter_kernel<<<(ET + 255) / 256, 256>>>(src, dst, cursor, col, E, N);

    const dim3 gemm_grid(256 / BN, (N + BM - 1) / BM);

    // ---- layer 1: GATConv(128 -> 64, heads=4) + bias + ELU ----
    sgemm<<<gemm_grid, 256>>>(x, W1, h, N, 256, 128);
    alpha_kernel<4, 64><<<(N * 4 * 32 + 255) / 256, 256>>>(h, as1, ad1, as, ad, N);
    aggregate_kernel<4, true><<<N, 256>>>(rowptr, col, as, ad, h, b1, x2);

    // ---- layer 2: GATConv(256 -> 256, heads=1) + bias ----
    sgemm<<<gemm_grid, 256>>>(x2, W2, h, N, 256, 256);
    alpha_kernel<1, 256><<<(N * 32 + 255) / 256, 256>>>(h, as2, ad2, as, ad, N);
    aggregate_kernel<1, false><<<N, 256>>>(rowptr, col, as, ad, h, b2, out);
}

// round 7
// speedup vs baseline: 3.1817x; 1.2738x over previous
#include <cuda_runtime.h>
#include <math.h>
#include <stdint.h>

// Problem constants: N=50000, E=800000, IN=128, HID=256, HEADS=4
#define NMAX 50000
#define EMAX 800000

// ---------------- device scratch (no allocations allowed) ----------------
__device__ float g_h   [NMAX * 256];
__device__ float g_x2  [NMAX * 256];
__device__ float g_as  [NMAX * 4];
__device__ float g_ad  [NMAX * 4];
__device__ int   g_cnt   [NMAX];
__device__ int   g_rowptr[NMAX + 1];
__device__ int   g_cursor[NMAX];
__device__ int   g_col   [EMAX + NMAX];

// ======================= CSR build =======================
__global__ void fill_int_kernel(int* __restrict__ p, int v, int n) {
    int i = blockIdx.x * blockDim.x + threadIdx.x;
    if (i < n) p[i] = v;
}

__global__ void count_kernel(const int* __restrict__ dst, int* __restrict__ cnt, int E) {
    int i = blockIdx.x * blockDim.x + threadIdx.x;
    if (i < E) atomicAdd(&cnt[dst[i]], 1);
}

__global__ __launch_bounds__(1024) void scan_kernel(
    const int* __restrict__ cnt, int* __restrict__ rowptr,
    int* __restrict__ cursor, int n)
{
    __shared__ int part[1024];
    const int tid = threadIdx.x;
    const int chunk = (n + 1023) >> 10;
    const int begin = tid * chunk;
    const int finish = min(begin + chunk, n);
    int s = 0;
    for (int i = begin; i < finish; i++) s += cnt[i];
    part[tid] = s;
    __syncthreads();
    for (int off = 1; off < 1024; off <<= 1) {
        int v = (tid >= off) ? part[tid - off] : 0;
        __syncthreads();
        part[tid] += v;
        __syncthreads();
    }
    int run = (tid == 0) ? 0 : part[tid - 1];
    for (int i = begin; i < finish; i++) {
        rowptr[i] = run;
        cursor[i] = run;
        run += cnt[i];
    }
    if (tid == 1023) rowptr[n] = part[1023];
}

__global__ void scatter_kernel(
    const int* __restrict__ src, const int* __restrict__ dst,
    int* __restrict__ cursor, int* __restrict__ col, int E, int n)
{
    int i = blockIdx.x * blockDim.x + threadIdx.x;
    int ET = E + n;
    if (i >= ET) return;
    int s, d;
    if (i < E) { s = src[i]; d = dst[i]; } else { s = d = i - E; }
    int p = atomicAdd(&cursor[d], 1);
    col[p] = s;
}

// ======================= 3xTF32 tensor-core GEMM =======================
// C[M,N] = A[M,K] @ B[K,N], fp32-accurate via Dekker split (hi.hi + hi.lo + lo.hi).
// BM=128, BN=128, BK=16, 256 threads = 8 warps (4 in M x 2 in N),
// warp tile 32x64, mma.sync.m16n8k8.tf32. Requires N%128==0, K%16==0.
#define PA 20     // As pitch (floats): [m][k], conflict-free frag loads
#define PB 132    // Bs pitch (floats): [k][n]

__device__ __forceinline__ float cvt_tf32(float x) {
    uint32_t o;
    asm("cvt.rna.tf32.f32 %0, %1;" : "=r"(o) : "f"(x));
    return __uint_as_float(o);
}

__device__ __forceinline__ void mma_tf32(
    float& c0, float& c1, float& c2, float& c3,
    float a0, float a1, float a2, float a3, float b0, float b1)
{
    asm volatile(
        "mma.sync.aligned.m16n8k8.row.col.f32.tf32.tf32.f32 "
        "{%0,%1,%2,%3}, {%4,%5,%6,%7}, {%8,%9}, {%0,%1,%2,%3};"
        : "+f"(c0), "+f"(c1), "+f"(c2), "+f"(c3)
        : "r"(__float_as_uint(a0)), "r"(__float_as_uint(a1)),
          "r"(__float_as_uint(a2)), "r"(__float_as_uint(a3)),
          "r"(__float_as_uint(b0)), "r"(__float_as_uint(b1)));
}

__global__ __launch_bounds__(256) void sgemm_tf32(
    const float* __restrict__ A, const float* __restrict__ B,
    float* __restrict__ C, int M, int N, int K)
{
    __shared__ float As_hi[128 * PA], As_lo[128 * PA];
    __shared__ float Bs_hi[16 * PB],  Bs_lo[16 * PB];

    const int tid = threadIdx.x;
    const int bm = blockIdx.y * 128;
    const int bn = blockIdx.x * 128;
    const int wid = tid >> 5;
    const int lane = tid & 31;
    const int grp = lane >> 2;       // 0..7
    const int tig = lane & 3;        // 0..3
    const int warp_m = (wid & 3) * 32;
    const int warp_n = (wid >> 2) * 64;

    float c[2][8][4];
#pragma unroll
    for (int mi = 0; mi < 2; mi++)
#pragma unroll
        for (int ni = 0; ni < 8; ni++)
#pragma unroll
            for (int q = 0; q < 4; q++) c[mi][ni][q] = 0.0f;

    const int T = K >> 4;
    float4 aR[2], bR[2];

    // ---- register-staged pipeline: load tile t+1 while computing tile t ----
    auto load_regs = [&](int k0) {
#pragma unroll
        for (int i = 0; i < 2; i++) {
            int idx = tid + i * 256;             // A: 0..511
            int row = idx >> 2, kq = idx & 3;    // 128 rows x 4 float4
            aR[i] = make_float4(0.f, 0.f, 0.f, 0.f);
            if (bm + row < M)
                aR[i] = *(const float4*)&A[(size_t)(bm + row) * K + k0 + kq * 4];
        }
#pragma unroll
        for (int i = 0; i < 2; i++) {
            int idx = tid + i * 256;             // B: 0..511
            int krow = idx >> 5, nq = idx & 31;  // 16 rows x 32 float4
            bR[i] = *(const float4*)&B[(size_t)(k0 + krow) * N + bn + nq * 4];
        }
    };
    auto store_smem = [&]() {
#pragma unroll
        for (int i = 0; i < 2; i++) {
            int idx = tid + i * 256;
            int row = idx >> 2, kq = idx & 3;
            float hx = cvt_tf32(aR[i].x), hy = cvt_tf32(aR[i].y);
            float hz = cvt_tf32(aR[i].z), hw = cvt_tf32(aR[i].w);
            *(float4*)&As_hi[row * PA + kq * 4] = make_float4(hx, hy, hz, hw);
            *(float4*)&As_lo[row * PA + kq * 4] = make_float4(
                cvt_tf32(aR[i].x - hx), cvt_tf32(aR[i].y - hy),
                cvt_tf32(aR[i].z - hz), cvt_tf32(aR[i].w - hw));
        }
#pragma unroll
        for (int i = 0; i < 2; i++) {
            int idx = tid + i * 256;
            int krow = idx >> 5, nq = idx & 31;
            float hx = cvt_tf32(bR[i].x), hy = cvt_tf32(bR[i].y);
            float hz = cvt_tf32(bR[i].z), hw = cvt_tf32(bR[i].w);
            *(float4*)&Bs_hi[krow * PB + nq * 4] = make_float4(hx, hy, hz, hw);
            *(float4*)&Bs_lo[krow * PB + nq * 4] = make_float4(
                cvt_tf32(bR[i].x - hx), cvt_tf32(bR[i].y - hy),
                cvt_tf32(bR[i].z - hz), cvt_tf32(bR[i].w - hw));
        }
    };

    load_regs(0);
    store_smem();
    __syncthreads();

    for (int t = 0; t < T; t++) {
        if (t + 1 < T) load_regs((t + 1) << 4);

#pragma unroll
        for (int ks = 0; ks < 16; ks += 8) {
            float ah[2][4], al[2][4];
#pragma unroll
            for (int mi = 0; mi < 2; mi++) {
                int rowA = warp_m + mi * 16 + grp;
                ah[mi][0] = As_hi[rowA * PA + ks + tig];
                ah[mi][1] = As_hi[(rowA + 8) * PA + ks + tig];
                ah[mi][2] = As_hi[rowA * PA + ks + tig + 4];
                ah[mi][3] = As_hi[(rowA + 8) * PA + ks + tig + 4];
                al[mi][0] = As_lo[rowA * PA + ks + tig];
                al[mi][1] = As_lo[(rowA + 8) * PA + ks + tig];
                al[mi][2] = As_lo[rowA * PA + ks + tig + 4];
                al[mi][3] = As_lo[(rowA + 8) * PA + ks + tig + 4];
            }
            float bh[8][2], bl[8][2];
#pragma unroll
            for (int ni = 0; ni < 8; ni++) {
                int nb = warp_n + ni * 8 + grp;
                bh[ni][0] = Bs_hi[(ks + tig) * PB + nb];
                bh[ni][1] = Bs_hi[(ks + tig + 4) * PB + nb];
                bl[ni][0] = Bs_lo[(ks + tig) * PB + nb];
                bl[ni][1] = Bs_lo[(ks + tig + 4) * PB + nb];
            }
#pragma unroll
            for (int mi = 0; mi < 2; mi++)
#pragma unroll
                for (int ni = 0; ni < 8; ni++) {
                    float* cc = c[mi][ni];
                    // correction terms first, hi*hi last
                    mma_tf32(cc[0], cc[1], cc[2], cc[3],
                             ah[mi][0], ah[mi][1], ah[mi][2], ah[mi][3],
                             bl[ni][0], bl[ni][1]);
                    mma_tf32(cc[0], cc[1], cc[2], cc[3],
                             al[mi][0], al[mi][1], al[mi][2], al[mi][3],
                             bh[ni][0], bh[ni][1]);
                    mma_tf32(cc[0], cc[1], cc[2], cc[3],
                             ah[mi][0], ah[mi][1], ah[mi][2], ah[mi][3],
                             bh[ni][0], bh[ni][1]);
                }
        }
        __syncthreads();
        if (t + 1 < T) {
            store_smem();
            __syncthreads();
        }
    }

    // ---- epilogue ----
#pragma unroll
    for (int mi = 0; mi < 2; mi++) {
        int row0 = bm + warp_m + mi * 16 + grp;
        int row1 = row0 + 8;
#pragma unroll
        for (int ni = 0; ni < 8; ni++) {
            int coln = bn + warp_n + ni * 8 + tig * 2;
            if (row0 < M)
                *(float2*)&C[(size_t)row0 * N + coln] = make_float2(c[mi][ni][0], c[mi][ni][1]);
            if (row1 < M)
                *(float2*)&C[(size_t)row1 * N + coln] = make_float2(c[mi][ni][2], c[mi][ni][3]);
        }
    }
}

// ============== per-node attention scalars: <h, a_src>, <h, a_dst> ==============
template <int H, int C>
__global__ __launch_bounds__(256) void alpha_kernel(
    const float* __restrict__ hfeat, const float* __restrict__ a_src,
    const float* __restrict__ a_dst, float* __restrict__ as_out,
    float* __restrict__ ad_out, int n)
{
    int warp = (blockIdx.x * blockDim.x + threadIdx.x) >> 5;
    int lane = threadIdx.x & 31;
    if (warp >= n * H) return;
    int node = warp / H, head = warp % H;
    const float* hp  = hfeat + (size_t)node * (H * C) + head * C;
    const float* asp = a_src + head * C;
    const float* adp = a_dst + head * C;
    float s1 = 0.0f, s2 = 0.0f;
#pragma unroll
    for (int c = lane; c < C; c += 32) {
        float v = hp[c];
        s1 += v * asp[c];
        s2 += v * adp[c];
    }
#pragma unroll
    for (int o = 16; o > 0; o >>= 1) {
        s1 += __shfl_xor_sync(0xFFFFFFFFu, s1, o);
        s2 += __shfl_xor_sync(0xFFFFFFFFu, s2, o);
    }
    if (lane == 0) { as_out[warp] = s1; ad_out[warp] = s2; }
}

// ============== warp-per-node gather aggregation ==============
// 32 lanes per dst node; lane owns 8 channels (2 x float4).
// Weights computed per 32-edge chunk, broadcast via shfl; per-head denominator
// falls out identically on every lane of that head.
template <int H, bool ELU>
__global__ __launch_bounds__(256) void agg_warp(
    const int* __restrict__ rowptr, const int* __restrict__ col,
    const float* __restrict__ as, const float* __restrict__ ad,
    const float* __restrict__ hfeat, const float* __restrict__ bias,
    float* __restrict__ out, int n)
{
    const int gw = (blockIdx.x * blockDim.x + threadIdx.x) >> 5;
    if (gw >= n) return;
    const int lane = threadIdx.x & 31;
    const int myhead = (H == 1) ? 0 : (lane >> 3);   // 8 lanes per head (H=4)

    const int start = rowptr[gw];
    const int end   = rowptr[gw + 1];

    float advv[H];
#pragma unroll
    for (int h = 0; h < H; h++) advv[h] = ad[gw * H + h];

    float4 acc0 = make_float4(0.f, 0.f, 0.f, 0.f);
    float4 acc1 = make_float4(0.f, 0.f, 0.f, 0.f);
    float den = 0.0f;

    for (int base = start; base < end; base += 32) {
        const int cnt = min(32, end - base);
        int s = 0;
        float wv[H];
#pragma unroll
        for (int h = 0; h < H; h++) wv[h] = 0.0f;
        if (lane < cnt) {
            s = col[base + lane];
#pragma unroll
            for (int h = 0; h < H; h++) {
                float e = as[s * H + h] + advv[h];
                e = e > 0.0f ? e : 0.2f * e;
                wv[h] = __expf(e);
            }
        }
#pragma unroll 4
        for (int j = 0; j < cnt; j++) {
            int sj = __shfl_sync(0xFFFFFFFFu, s, j);
            float w;
            if (H == 1) {
                w = __shfl_sync(0xFFFFFFFFu, wv[0], j);
            } else {
                float w0 = __shfl_sync(0xFFFFFFFFu, wv[0], j);
                float w1 = __shfl_sync(0xFFFFFFFFu, wv[1], j);
                float w2 = __shfl_sync(0xFFFFFFFFu, wv[2], j);
                float w3 = __shfl_sync(0xFFFFFFFFu, wv[3], j);
                w = (myhead == 0) ? w0 : (myhead == 1) ? w1 : (myhead == 2) ? w2 : w3;
            }
            den += w;
            const float4* hp = reinterpret_cast<const float4*>(hfeat + (size_t)sj * 256) + lane * 2;
            float4 v0 = hp[0];
            float4 v1 = hp[1];
            acc0.x += w * v0.x; acc0.y += w * v0.y; acc0.z += w * v0.z; acc0.w += w * v0.w;
            acc1.x += w * v1.x; acc1.y += w * v1.y; acc1.z += w * v1.z; acc1.w += w * v1.w;
        }
    }

    const float inv = 1.0f / (den + 1e-16f);
    const float4* bp = reinterpret_cast<const float4*>(bias) + lane * 2;
    float4 b0 = bp[0], b1 = bp[1];
    float4 o0, o1;
    o0.x = acc0.x * inv + b0.x; o0.y = acc0.y * inv + b0.y;
    o0.z = acc0.z * inv + b0.z; o0.w = acc0.w * inv + b0.w;
    o1.x = acc1.x * inv + b1.x; o1.y = acc1.y * inv + b1.y;
    o1.z = acc1.z * inv + b1.z; o1.w = acc1.w * inv + b1.w;
    if (ELU) {
        o0.x = o0.x > 0.f ? o0.x : expm1f(o0.x);
        o0.y = o0.y > 0.f ? o0.y : expm1f(o0.y);
        o0.z = o0.z > 0.f ? o0.z : expm1f(o0.z);
        o0.w = o0.w > 0.f ? o0.w : expm1f(o0.w);
        o1.x = o1.x > 0.f ? o1.x : expm1f(o1.x);
        o1.y = o1.y > 0.f ? o1.y : expm1f(o1.y);
        o1.z = o1.z > 0.f ? o1.z : expm1f(o1.z);
        o1.w = o1.w > 0.f ? o1.w : expm1f(o1.w);
    }
    float4* op = reinterpret_cast<float4*>(out + (size_t)gw * 256) + lane * 2;
    op[0] = o0;
    op[1] = o1;
}

// ======================= launch =======================
extern "C" void kernel_launch(void* const* d_in, const int* in_sizes, int n_in,
                              void* d_out, int out_size)
{
    const float* x   = (const float*)d_in[0];
    const int*   ei  = (const int*)  d_in[1];
    const float* W1  = (const float*)d_in[2];
    const float* as1 = (const float*)d_in[3];
    const float* ad1 = (const float*)d_in[4];
    const float* b1  = (const float*)d_in[5];
    const float* W2  = (const float*)d_in[6];
    const float* as2 = (const float*)d_in[7];
    const float* ad2 = (const float*)d_in[8];
    const float* b2  = (const float*)d_in[9];
    float* out = (float*)d_out;

    const int N = in_sizes[0] / 128;
    const int E = in_sizes[1] / 2;
    const int* src = ei;
    const int* dst = ei + E;
    const int ET = E + N;

    float *h, *x2, *as, *ad;
    int *cnt, *rowptr, *cursor, *col;
    cudaGetSymbolAddress((void**)&h,      g_h);
    cudaGetSymbolAddress((void**)&x2,     g_x2);
    cudaGetSymbolAddress((void**)&as,     g_as);
    cudaGetSymbolAddress((void**)&ad,     g_ad);
    cudaGetSymbolAddress((void**)&cnt,    g_cnt);
    cudaGetSymbolAddress((void**)&rowptr, g_rowptr);
    cudaGetSymbolAddress((void**)&cursor, g_cursor);
    cudaGetSymbolAddress((void**)&col,    g_col);

    // ---- CSR build (counts init to 1 = self-loop) ----
    fill_int_kernel<<<(N + 255) / 256, 256>>>(cnt, 1, N);
    count_kernel<<<(E + 255) / 256, 256>>>(dst, cnt, E);
    scan_kernel<<<1, 1024>>>(cnt, rowptr, cursor, N);
    scatter_kernel<<<(ET + 255) / 256, 256>>>(src, dst, cursor, col, E, N);

    const dim3 gemm_grid(2, (N + 127) / 128);
    const int agg_blocks = (N * 32 + 255) / 256;

    // ---- layer 1: GATConv(128 -> 64, heads=4) + bias + ELU ----
    sgemm_tf32<<<gemm_grid, 256>>>(x, W1, h, N, 256, 128);
    alpha_kernel<4, 64><<<(N * 4 * 32 + 255) / 256, 256>>>(h, as1, ad1, as, ad, N);
    agg_warp<4, true><<<agg_blocks, 256>>>(rowptr, col, as, ad, h, b1, x2, N);

    // ---- layer 2: GATConv(256 -> 256, heads=1) + bias ----
    sgemm_tf32<<<gemm_grid, 256>>>(x2, W2, h, N, 256, 256);
    alpha_kernel<1, 256><<<(N * 32 + 255) / 256, 256>>>(h, as2, ad2, as, ad, N);
    agg_warp<1, false><<<agg_blocks, 256>>>(rowptr, col, as, ad, h, b2, out, N);
}

// round 8
// speedup vs baseline: 3.3179x; 1.0428x over previous
#include <cuda_runtime.h>
#include <math.h>
#include <stdint.h>

// Problem constants: N=50000, E=800000, IN=128, HID=256, HEADS=4
#define NMAX 50000
#define EMAX 800000

// ---------------- device scratch (no allocations allowed) ----------------
__device__ float g_h   [NMAX * 256];
__device__ float g_x2  [NMAX * 256];
__device__ float g_as1 [NMAX * 4];
__device__ float g_ad1 [NMAX * 4];
__device__ float g_as2 [NMAX];
__device__ float g_ad2 [NMAX];
__device__ int   g_cnt   [NMAX];
__device__ int   g_rowptr[NMAX + 1];
__device__ int   g_cursor[NMAX];
__device__ int   g_col   [EMAX + NMAX];

// ======================= small fills =======================
__global__ void fill_int_kernel(int* __restrict__ p, int v, int n) {
    int i = blockIdx.x * blockDim.x + threadIdx.x;
    if (i < n) p[i] = v;
}
__global__ void fill_f_kernel(float* __restrict__ p, float v, int n) {
    int i = blockIdx.x * blockDim.x + threadIdx.x;
    if (i < n) p[i] = v;
}

__global__ void count_kernel(const int* __restrict__ dst, int* __restrict__ cnt, int E) {
    int i = blockIdx.x * blockDim.x + threadIdx.x;
    if (i < E) atomicAdd(&cnt[dst[i]], 1);
}

__global__ __launch_bounds__(1024) void scan_kernel(
    const int* __restrict__ cnt, int* __restrict__ rowptr,
    int* __restrict__ cursor, int n)
{
    __shared__ int part[1024];
    const int tid = threadIdx.x;
    const int chunk = (n + 1023) >> 10;
    const int begin = tid * chunk;
    const int finish = min(begin + chunk, n);
    int s = 0;
    for (int i = begin; i < finish; i++) s += cnt[i];
    part[tid] = s;
    __syncthreads();
    for (int off = 1; off < 1024; off <<= 1) {
        int v = (tid >= off) ? part[tid - off] : 0;
        __syncthreads();
        part[tid] += v;
        __syncthreads();
    }
    int run = (tid == 0) ? 0 : part[tid - 1];
    for (int i = begin; i < finish; i++) {
        rowptr[i] = run;
        cursor[i] = run;
        run += cnt[i];
    }
    if (tid == 1023) rowptr[n] = part[1023];
}

__global__ void scatter_kernel(
    const int* __restrict__ src, const int* __restrict__ dst,
    int* __restrict__ cursor, int* __restrict__ col, int E, int n)
{
    int i = blockIdx.x * blockDim.x + threadIdx.x;
    int ET = E + n;
    if (i >= ET) return;
    int s, d;
    if (i < E) { s = src[i]; d = dst[i]; } else { s = d = i - E; }
    int p = atomicAdd(&cursor[d], 1);
    col[p] = s;
}

// ======================= 3xTF32 tensor-core GEMM + fused alpha =======================
// C[M,N] = A[M,K] @ B[K,N]; also emits as/ad = <C_row, a_src/a_dst> per head.
// H=4: each 64-col warp tile = one head -> unique writer, plain store.
// H=1: dot spans 256 cols -> 4 partial writers -> atomicAdd (buffers pre-zeroed).
#define PA 20
#define PB 132

__device__ __forceinline__ float cvt_tf32(float x) {
    uint32_t o;
    asm("cvt.rna.tf32.f32 %0, %1;" : "=r"(o) : "f"(x));
    return __uint_as_float(o);
}

__device__ __forceinline__ void mma_tf32(
    float& c0, float& c1, float& c2, float& c3,
    float a0, float a1, float a2, float a3, float b0, float b1)
{
    asm volatile(
        "mma.sync.aligned.m16n8k8.row.col.f32.tf32.tf32.f32 "
        "{%0,%1,%2,%3}, {%4,%5,%6,%7}, {%8,%9}, {%0,%1,%2,%3};"
        : "+f"(c0), "+f"(c1), "+f"(c2), "+f"(c3)
        : "r"(__float_as_uint(a0)), "r"(__float_as_uint(a1)),
          "r"(__float_as_uint(a2)), "r"(__float_as_uint(a3)),
          "r"(__float_as_uint(b0)), "r"(__float_as_uint(b1)));
}

template <int H>
__global__ __launch_bounds__(256) void sgemm_tf32(
    const float* __restrict__ A, const float* __restrict__ B,
    float* __restrict__ C,
    const float* __restrict__ avec_src, const float* __restrict__ avec_dst,
    float* __restrict__ as_out, float* __restrict__ ad_out,
    int M, int N, int K)
{
    __shared__ float As_hi[128 * PA], As_lo[128 * PA];
    __shared__ float Bs_hi[16 * PB],  Bs_lo[16 * PB];

    const int tid = threadIdx.x;
    const int bm = blockIdx.y * 128;
    const int bn = blockIdx.x * 128;
    const int wid = tid >> 5;
    const int lane = tid & 31;
    const int grp = lane >> 2;       // 0..7
    const int tig = lane & 3;        // 0..3
    const int warp_m = (wid & 3) * 32;
    const int warp_n = (wid >> 2) * 64;

    float c[2][8][4];
#pragma unroll
    for (int mi = 0; mi < 2; mi++)
#pragma unroll
        for (int ni = 0; ni < 8; ni++)
#pragma unroll
            for (int q = 0; q < 4; q++) c[mi][ni][q] = 0.0f;

    const int T = K >> 4;
    float4 aR[2], bR[2];

    auto load_regs = [&](int k0) {
#pragma unroll
        for (int i = 0; i < 2; i++) {
            int idx = tid + i * 256;
            int row = idx >> 2, kq = idx & 3;
            aR[i] = make_float4(0.f, 0.f, 0.f, 0.f);
            if (bm + row < M)
                aR[i] = *(const float4*)&A[(size_t)(bm + row) * K + k0 + kq * 4];
        }
#pragma unroll
        for (int i = 0; i < 2; i++) {
            int idx = tid + i * 256;
            int krow = idx >> 5, nq = idx & 31;
            bR[i] = *(const float4*)&B[(size_t)(k0 + krow) * N + bn + nq * 4];
        }
    };
    auto store_smem = [&]() {
#pragma unroll
        for (int i = 0; i < 2; i++) {
            int idx = tid + i * 256;
            int row = idx >> 2, kq = idx & 3;
            float hx = cvt_tf32(aR[i].x), hy = cvt_tf32(aR[i].y);
            float hz = cvt_tf32(aR[i].z), hw = cvt_tf32(aR[i].w);
            *(float4*)&As_hi[row * PA + kq * 4] = make_float4(hx, hy, hz, hw);
            *(float4*)&As_lo[row * PA + kq * 4] = make_float4(
                cvt_tf32(aR[i].x - hx), cvt_tf32(aR[i].y - hy),
                cvt_tf32(aR[i].z - hz), cvt_tf32(aR[i].w - hw));
        }
#pragma unroll
        for (int i = 0; i < 2; i++) {
            int idx = tid + i * 256;
            int krow = idx >> 5, nq = idx & 31;
            float hx = cvt_tf32(bR[i].x), hy = cvt_tf32(bR[i].y);
            float hz = cvt_tf32(bR[i].z), hw = cvt_tf32(bR[i].w);
            *(float4*)&Bs_hi[krow * PB + nq * 4] = make_float4(hx, hy, hz, hw);
            *(float4*)&Bs_lo[krow * PB + nq * 4] = make_float4(
                cvt_tf32(bR[i].x - hx), cvt_tf32(bR[i].y - hy),
                cvt_tf32(bR[i].z - hz), cvt_tf32(bR[i].w - hw));
        }
    };

    load_regs(0);
    store_smem();
    __syncthreads();

    for (int t = 0; t < T; t++) {
        if (t + 1 < T) load_regs((t + 1) << 4);

#pragma unroll
        for (int ks = 0; ks < 16; ks += 8) {
            float ah[2][4], al[2][4];
#pragma unroll
            for (int mi = 0; mi < 2; mi++) {
                int rowA = warp_m + mi * 16 + grp;
                ah[mi][0] = As_hi[rowA * PA + ks + tig];
                ah[mi][1] = As_hi[(rowA + 8) * PA + ks + tig];
                ah[mi][2] = As_hi[rowA * PA + ks + tig + 4];
                ah[mi][3] = As_hi[(rowA + 8) * PA + ks + tig + 4];
                al[mi][0] = As_lo[rowA * PA + ks + tig];
                al[mi][1] = As_lo[(rowA + 8) * PA + ks + tig];
                al[mi][2] = As_lo[rowA * PA + ks + tig + 4];
                al[mi][3] = As_lo[(rowA + 8) * PA + ks + tig + 4];
            }
            float bh[8][2], bl[8][2];
#pragma unroll
            for (int ni = 0; ni < 8; ni++) {
                int nb = warp_n + ni * 8 + grp;
                bh[ni][0] = Bs_hi[(ks + tig) * PB + nb];
                bh[ni][1] = Bs_hi[(ks + tig + 4) * PB + nb];
                bl[ni][0] = Bs_lo[(ks + tig) * PB + nb];
                bl[ni][1] = Bs_lo[(ks + tig + 4) * PB + nb];
            }
#pragma unroll
            for (int mi = 0; mi < 2; mi++)
#pragma unroll
                for (int ni = 0; ni < 8; ni++) {
                    float* cc = c[mi][ni];
                    mma_tf32(cc[0], cc[1], cc[2], cc[3],
                             ah[mi][0], ah[mi][1], ah[mi][2], ah[mi][3],
                             bl[ni][0], bl[ni][1]);
                    mma_tf32(cc[0], cc[1], cc[2], cc[3],
                             al[mi][0], al[mi][1], al[mi][2], al[mi][3],
                             bh[ni][0], bh[ni][1]);
                    mma_tf32(cc[0], cc[1], cc[2], cc[3],
                             ah[mi][0], ah[mi][1], ah[mi][2], ah[mi][3],
                             bh[ni][0], bh[ni][1]);
                }
        }
        __syncthreads();
        if (t + 1 < T) {
            store_smem();
            __syncthreads();
        }
    }

    // ---- epilogue: store C ----
#pragma unroll
    for (int mi = 0; mi < 2; mi++) {
        int row0 = bm + warp_m + mi * 16 + grp;
        int row1 = row0 + 8;
#pragma unroll
        for (int ni = 0; ni < 8; ni++) {
            int coln = bn + warp_n + ni * 8 + tig * 2;
            if (row0 < M)
                *(float2*)&C[(size_t)row0 * N + coln] = make_float2(c[mi][ni][0], c[mi][ni][1]);
            if (row1 < M)
                *(float2*)&C[(size_t)row1 * N + coln] = make_float2(c[mi][ni][2], c[mi][ni][3]);
        }
    }

    // ---- fused alpha: per-row dots with a_src / a_dst over this tile's columns ----
    // Load the 16 attention-vector entries this thread's columns touch.
    float av0[8], av1[8], dv0[8], dv1[8];
    const int head = (H == 4) ? ((bn + warp_n) >> 6) : 0;
#pragma unroll
    for (int ni = 0; ni < 8; ni++) {
        int coln = bn + warp_n + ni * 8 + tig * 2;
        int ai = (H == 4) ? (head * 64 + (coln & 63)) : coln;
        av0[ni] = avec_src[ai];
        av1[ni] = avec_src[ai + 1];
        dv0[ni] = avec_dst[ai];
        dv1[ni] = avec_dst[ai + 1];
    }
#pragma unroll
    for (int mi = 0; mi < 2; mi++) {
        float sA0 = 0.f, sD0 = 0.f, sA1 = 0.f, sD1 = 0.f;
#pragma unroll
        for (int ni = 0; ni < 8; ni++) {
            sA0 += c[mi][ni][0] * av0[ni] + c[mi][ni][1] * av1[ni];
            sD0 += c[mi][ni][0] * dv0[ni] + c[mi][ni][1] * dv1[ni];
            sA1 += c[mi][ni][2] * av0[ni] + c[mi][ni][3] * av1[ni];
            sD1 += c[mi][ni][2] * dv0[ni] + c[mi][ni][3] * dv1[ni];
        }
        // reduce across the 4 tig lanes (adjacent lanes within each grp nibble)
#pragma unroll
        for (int o = 1; o < 4; o <<= 1) {
            sA0 += __shfl_xor_sync(0xFFFFFFFFu, sA0, o);
            sD0 += __shfl_xor_sync(0xFFFFFFFFu, sD0, o);
            sA1 += __shfl_xor_sync(0xFFFFFFFFu, sA1, o);
            sD1 += __shfl_xor_sync(0xFFFFFFFFu, sD1, o);
        }
        if (tig == 0) {
            int row0 = bm + warp_m + mi * 16 + grp;
            int row1 = row0 + 8;
            if (H == 4) {
                if (row0 < M) { as_out[row0 * 4 + head] = sA0; ad_out[row0 * 4 + head] = sD0; }
                if (row1 < M) { as_out[row1 * 4 + head] = sA1; ad_out[row1 * 4 + head] = sD1; }
            } else {
                if (row0 < M) { atomicAdd(&as_out[row0], sA0); atomicAdd(&ad_out[row0], sD0); }
                if (row1 < M) { atomicAdd(&as_out[row1], sA1); atomicAdd(&ad_out[row1], sD1); }
            }
        }
    }
}

// ============== warp-per-node gather aggregation ==============
template <int H, bool ELU>
__global__ __launch_bounds__(256) void agg_warp(
    const int* __restrict__ rowptr, const int* __restrict__ col,
    const float* __restrict__ as, const float* __restrict__ ad,
    const float* __restrict__ hfeat, const float* __restrict__ bias,
    float* __restrict__ out, int n)
{
    const int gw = (blockIdx.x * blockDim.x + threadIdx.x) >> 5;
    if (gw >= n) return;
    const int lane = threadIdx.x & 31;
    const int myhead = (H == 1) ? 0 : (lane >> 3);

    const int start = rowptr[gw];
    const int end   = rowptr[gw + 1];

    float advv[H];
#pragma unroll
    for (int h = 0; h < H; h++) advv[h] = ad[gw * H + h];

    float4 acc0 = make_float4(0.f, 0.f, 0.f, 0.f);
    float4 acc1 = make_float4(0.f, 0.f, 0.f, 0.f);
    float den = 0.0f;

    for (int base = start; base < end; base += 32) {
        const int cnt = min(32, end - base);
        int s = 0;
        float wv[H];
#pragma unroll
        for (int h = 0; h < H; h++) wv[h] = 0.0f;
        if (lane < cnt) {
            s = col[base + lane];
#pragma unroll
            for (int h = 0; h < H; h++) {
                float e = as[s * H + h] + advv[h];
                e = e > 0.0f ? e : 0.2f * e;
                wv[h] = __expf(e);
            }
        }
#pragma unroll 4
        for (int j = 0; j < cnt; j++) {
            int sj = __shfl_sync(0xFFFFFFFFu, s, j);
            float w;
            if (H == 1) {
                w = __shfl_sync(0xFFFFFFFFu, wv[0], j);
            } else {
                float w0 = __shfl_sync(0xFFFFFFFFu, wv[0], j);
                float w1 = __shfl_sync(0xFFFFFFFFu, wv[1], j);
                float w2 = __shfl_sync(0xFFFFFFFFu, wv[2], j);
                float w3 = __shfl_sync(0xFFFFFFFFu, wv[3], j);
                w = (myhead == 0) ? w0 : (myhead == 1) ? w1 : (myhead == 2) ? w2 : w3;
            }
            den += w;
            const float4* hp = reinterpret_cast<const float4*>(hfeat + (size_t)sj * 256) + lane * 2;
            float4 v0 = hp[0];
            float4 v1 = hp[1];
            acc0.x += w * v0.x; acc0.y += w * v0.y; acc0.z += w * v0.z; acc0.w += w * v0.w;
            acc1.x += w * v1.x; acc1.y += w * v1.y; acc1.z += w * v1.z; acc1.w += w * v1.w;
        }
    }

    const float inv = 1.0f / (den + 1e-16f);
    const float4* bp = reinterpret_cast<const float4*>(bias) + lane * 2;
    float4 b0 = bp[0], b1 = bp[1];
    float4 o0, o1;
    o0.x = acc0.x * inv + b0.x; o0.y = acc0.y * inv + b0.y;
    o0.z = acc0.z * inv + b0.z; o0.w = acc0.w * inv + b0.w;
    o1.x = acc1.x * inv + b1.x; o1.y = acc1.y * inv + b1.y;
    o1.z = acc1.z * inv + b1.z; o1.w = acc1.w * inv + b1.w;
    if (ELU) {
        o0.x = o0.x > 0.f ? o0.x : expm1f(o0.x);
        o0.y = o0.y > 0.f ? o0.y : expm1f(o0.y);
        o0.z = o0.z > 0.f ? o0.z : expm1f(o0.z);
        o0.w = o0.w > 0.f ? o0.w : expm1f(o0.w);
        o1.x = o1.x > 0.f ? o1.x : expm1f(o1.x);
        o1.y = o1.y > 0.f ? o1.y : expm1f(o1.y);
        o1.z = o1.z > 0.f ? o1.z : expm1f(o1.z);
        o1.w = o1.w > 0.f ? o1.w : expm1f(o1.w);
    }
    float4* op = reinterpret_cast<float4*>(out + (size_t)gw * 256) + lane * 2;
    op[0] = o0;
    op[1] = o1;
}

// ======================= launch =======================
extern "C" void kernel_launch(void* const* d_in, const int* in_sizes, int n_in,
                              void* d_out, int out_size)
{
    const float* x   = (const float*)d_in[0];
    const int*   ei  = (const int*)  d_in[1];
    const float* W1  = (const float*)d_in[2];
    const float* as1v = (const float*)d_in[3];
    const float* ad1v = (const float*)d_in[4];
    const float* b1  = (const float*)d_in[5];
    const float* W2  = (const float*)d_in[6];
    const float* as2v = (const float*)d_in[7];
    const float* ad2v = (const float*)d_in[8];
    const float* b2  = (const float*)d_in[9];
    float* out = (float*)d_out;

    const int N = in_sizes[0] / 128;
    const int E = in_sizes[1] / 2;
    const int* src = ei;
    const int* dst = ei + E;
    const int ET = E + N;

    float *h, *x2, *as1, *ad1, *as2, *ad2;
    int *cnt, *rowptr, *cursor, *col;
    cudaGetSymbolAddress((void**)&h,      g_h);
    cudaGetSymbolAddress((void**)&x2,     g_x2);
    cudaGetSymbolAddress((void**)&as1,    g_as1);
    cudaGetSymbolAddress((void**)&ad1,    g_ad1);
    cudaGetSymbolAddress((void**)&as2,    g_as2);
    cudaGetSymbolAddress((void**)&ad2,    g_ad2);
    cudaGetSymbolAddress((void**)&cnt,    g_cnt);
    cudaGetSymbolAddress((void**)&rowptr, g_rowptr);
    cudaGetSymbolAddress((void**)&cursor, g_cursor);
    cudaGetSymbolAddress((void**)&col,    g_col);

    // Lazily-created side stream + fork/join events (resources only; the
    // launched GPU work is identical on every call).
    static cudaStream_t s_side = nullptr;
    static cudaEvent_t  s_fork = nullptr, s_join = nullptr;
    if (s_side == nullptr) {
        cudaStreamCreateWithFlags(&s_side, cudaStreamNonBlocking);
        cudaEventCreateWithFlags(&s_fork, cudaEventDisableTiming);
        cudaEventCreateWithFlags(&s_join, cudaEventDisableTiming);
    }

    const dim3 gemm_grid(2, (N + 127) / 128);
    const int agg_blocks = (N * 32 + 255) / 256;

    // ---- fork: CSR build + alpha2 zero-init on side stream ----
    cudaEventRecord(s_fork, 0);
    cudaStreamWaitEvent(s_side, s_fork, 0);
    fill_int_kernel<<<(N + 255) / 256, 256, 0, s_side>>>(cnt, 1, N);
    count_kernel<<<(E + 255) / 256, 256, 0, s_side>>>(dst, cnt, E);
    scan_kernel<<<1, 1024, 0, s_side>>>(cnt, rowptr, cursor, N);
    scatter_kernel<<<(ET + 255) / 256, 256, 0, s_side>>>(src, dst, cursor, col, E, N);
    fill_f_kernel<<<(N + 255) / 256, 256, 0, s_side>>>(as2, 0.0f, N);
    fill_f_kernel<<<(N + 255) / 256, 256, 0, s_side>>>(ad2, 0.0f, N);
    cudaEventRecord(s_join, s_side);

    // ---- main stream: layer-1 GEMM (+fused alpha1) runs concurrently ----
    sgemm_tf32<4><<<gemm_grid, 256>>>(x, W1, h, as1v, ad1v, as1, ad1, N, 256, 128);

    // join before aggregation (needs CSR)
    cudaStreamWaitEvent(0, s_join, 0);
    agg_warp<4, true><<<agg_blocks, 256>>>(rowptr, col, as1, ad1, h, b1, x2, N);

    // ---- layer 2: GEMM (+fused alpha2 via atomics into zeroed buffers) ----
    sgemm_tf32<1><<<gemm_grid, 256>>>(x2, W2, h, as2v, ad2v, as2, ad2, N, 256, 256);
    agg_warp<1, false><<<agg_blocks, 256>>>(rowptr, col, as2, ad2, h, b2, out, N);
}